// round 9
// baseline (speedup 1.0000x reference)
#include <cuda_runtime.h>
#include <math.h>

// ---------------------------------------------------------------------------
// Problem constants
// ---------------------------------------------------------------------------
constexpr int BB = 32;      // batch
constexpr int NS = 128;     // slots
constexpr int NF = 4096;    // features
constexpr int DD = 256;     // slot dim
constexpr int HH = 1024;    // mlp hidden

// ---------------------------------------------------------------------------
// Device scratch (static globals: allocation-free, graph-safe)
// ---------------------------------------------------------------------------
__device__ float g_h[4][64];                       // per-head time-MLP hidden
__device__ float g_W[983040];                      // Wq | Wg | Wf0 | Wf1 (row-major [dout,din])
__device__ float g_catA[(size_t)BB * NS * 2 * DD]; // [lnA(slots) , f_attn]
__device__ float g_catF[(size_t)BB * NS * 2 * DD]; // [lnF(slots) , f_attn]
__device__ float g_q[(size_t)BB * NS * DD];
__device__ float g_L[(size_t)BB * NS * NF];        // logits, then probabilities (in-place)
__device__ float g_cmax[(size_t)BB * NF];
__device__ float g_csum[(size_t)BB * NF];
__device__ float g_S[(size_t)BB * NS];
__device__ float g_ffh[(size_t)BB * NS * HH];

// W offsets inside g_W
constexpr int OFF_WQ  = 0;          // 256*256
constexpr int OFF_WG  = 65536;      // 256*512
constexpr int OFF_WF0 = 196608;     // 1024*512
constexpr int OFF_WF1 = 720896;     // 256*1024

// ---------------------------------------------------------------------------
// Helpers
// ---------------------------------------------------------------------------
__device__ __forceinline__ float block_sum(float v, float* red) {
    __syncthreads();
    int lane = threadIdx.x & 31, w = threadIdx.x >> 5;
    #pragma unroll
    for (int o = 16; o; o >>= 1) v += __shfl_xor_sync(0xffffffffu, v, o);
    if (lane == 0) red[w] = v;
    __syncthreads();
    float tot = 0.f;
    int nw = (blockDim.x + 31) >> 5;
    for (int i = 0; i < nw; i++) tot += red[i];
    return tot;
}

// Packed dual-fp32 FMA: acc = a*b + acc  (elementwise on f32x2). Exact fp32.
__device__ __forceinline__ void ffma2(unsigned long long& acc,
                                      unsigned long long a,
                                      unsigned long long b) {
    asm("fma.rn.f32x2 %0, %1, %2, %0;" : "+l"(acc) : "l"(a), "l"(b));
}

// ---------------------------------------------------------------------------
// Kernel 1: sinusoidal embedding + 2-layer SiLU MLP for all 4 heads
// ---------------------------------------------------------------------------
__global__ void time_mlp_kernel(
    const float* __restrict__ t_ptr,
    const float* qw0, const float* qb0, const float* qw1, const float* qb1,
    const float* gw0, const float* gb0, const float* gw1, const float* gb1,
    const float* f0w0, const float* f0b0, const float* f0w1, const float* f0b1,
    const float* f1w0, const float* f1b0, const float* f1w1, const float* f1b1)
{
    const float* w0s[4] = {qw0, gw0, f0w0, f1w0};
    const float* b0s[4] = {qb0, gb0, f0b0, f1b0};
    const float* w1s[4] = {qw1, gw1, f0w1, f1w1};
    const float* b1s[4] = {qb1, gb1, f0b1, f1b1};
    int head = blockIdx.x;
    const float* w0 = w0s[head]; const float* b0 = b0s[head];
    const float* w1 = w1s[head]; const float* b1 = b1s[head];

    __shared__ float emb[257];
    __shared__ float h0[64];
    int tid = threadIdx.x;
    float t = t_ptr[0];
    if (tid == 0) emb[0] = t;
    const float fscale = -logf(10000.0f) / 128.0f;
    for (int i = tid; i < 128; i += 64) {
        float w = fscale * (float)i * t;
        emb[1 + i]   = sinf(w);
        emb[129 + i] = cosf(w);
    }
    __syncthreads();
    float s = b0[tid];
    for (int j = 0; j < 257; j++) s += w0[tid * 257 + j] * emb[j];
    h0[tid] = s / (1.f + expf(-s));          // silu
    __syncthreads();
    float s2 = b1[tid];
    #pragma unroll 8
    for (int j = 0; j < 64; j++) s2 += w1[tid * 64 + j] * h0[j];
    g_h[head][tid] = s2 / (1.f + expf(-s2)); // silu
}

// ---------------------------------------------------------------------------
// Kernel 2: W = wp @ h + bp for all heads (983040 rows x 64) -> g_W
// ---------------------------------------------------------------------------
__global__ __launch_bounds__(256) void wproj_kernel(
    const float* __restrict__ qwp,  const float* __restrict__ qbp,
    const float* __restrict__ gwp,  const float* __restrict__ gbp,
    const float* __restrict__ f0wp, const float* __restrict__ f0bp,
    const float* __restrict__ f1wp, const float* __restrict__ f1bp)
{
    long long r = (long long)blockIdx.x * 256 + threadIdx.x;
    int head; const float* wp; const float* bp; long long lr;
    if (r < 65536)       { head = 0; wp = qwp;  bp = qbp;  lr = r; }
    else if (r < 196608) { head = 1; wp = gwp;  bp = gbp;  lr = r - 65536; }
    else if (r < 720896) { head = 2; wp = f0wp; bp = f0bp; lr = r - 196608; }
    else                 { head = 3; wp = f1wp; bp = f1bp; lr = r - 720896; }

    __shared__ float hs[64];
    if (threadIdx.x < 64) hs[threadIdx.x] = g_h[head][threadIdx.x];
    __syncthreads();

    const float4* w4 = (const float4*)(wp + lr * 64);
    float s = bp[lr];
    #pragma unroll
    for (int j = 0; j < 16; j++) {
        float4 x = w4[j];
        s += x.x * hs[4 * j] + x.y * hs[4 * j + 1] + x.z * hs[4 * j + 2] + x.w * hs[4 * j + 3];
    }
    g_W[r] = s;
}

// ---------------------------------------------------------------------------
// Kernel 3: LayerNorm -> first halves of g_catA (lnA affine) / g_catF (lnF)
// ---------------------------------------------------------------------------
__global__ __launch_bounds__(256) void ln_kernel(
    const float* __restrict__ slots,
    const float* __restrict__ aw, const float* __restrict__ ab,
    const float* __restrict__ fw, const float* __restrict__ fb)
{
    __shared__ float red[8];
    long long row = blockIdx.x;
    int d = threadIdx.x;
    float x = slots[row * 256 + d];
    float mu  = block_sum(x, red) * (1.f / 256.f);
    float dv  = x - mu;
    float var = block_sum(dv * dv, red) * (1.f / 256.f);
    float xh  = dv * rsqrtf(var + 1e-5f);
    g_catA[row * 512 + d] = xh * aw[d] + ab[d];
    g_catF[row * 512 + d] = xh * fw[d] + fb[d];
}

// ---------------------------------------------------------------------------
// Double-buffered SGEMM on packed f32x2 (FFMA2).
//   BTR=true : C[M,N] = epi(alpha * A[M,K] @ B[N,K]^T)   (both K-contiguous)
//   BTR=false: C[M,N] = epi(alpha * A[M,K] @ B[K,N])     (B N-contiguous)
// A is stored DUPLICATED in smem ((v,v) pairs) so packed broadcasts are
// direct LDS; accumulators are f32x2 pairs along N. Exact fp32 arithmetic.
// EPI: 0 store | 1 relu | 2 aux*sigmoid(v) | 3 C+=v
//      4 v/(aux[row]+1e-8) -> C and C2  (attention epilogue)
// ---------------------------------------------------------------------------
template<int BM, int BN, int BK, int TM, int TN, int THREADS, bool BTR, int EPI>
__global__ __launch_bounds__(THREADS) void gemm2(
    const float* __restrict__ A, int lda, long long sA,
    const float* __restrict__ B, int ldb, long long sB,
    float* __restrict__ C, int ldc, long long sC,
    int K, float alpha,
    const float* __restrict__ aux, long long sAux, int ldAux,
    float* __restrict__ C2)
{
    static_assert((BM / TM) * (BN / TN) == THREADS, "thread mapping");
    static_assert(TM % 2 == 0 && TN % 2 == 0 && (TN / 2) % 2 == 0, "pairing");
    constexpr int AW = 2 * BM + 4;          // duplicated A row width (floats)
    constexpr int BW = BN + 4;
    constexpr int N4A = (BM * BK) / (4 * THREADS);
    constexpr int N4B = (BK * BN) / (4 * THREADS);
    static_assert(N4A >= 1 && N4B >= 1, "tile/thread mismatch");

    __shared__ __align__(16) float Asd[2][BK][AW];
    __shared__ __align__(16) float Bs[2][BK][BW];

    const int t = threadIdx.x;
    const int z = blockIdx.z;
    A += sA * z; B += sB * z; C += sC * z;
    if (EPI == 4 && C2) C2 += sC * z;

    const long long brow = (long long)blockIdx.y * BM;
    const int bcol = blockIdx.x * BN;

    float4 ra[N4A], rb[N4B];

    auto ldAB = [&](int k0) {
        #pragma unroll
        for (int u = 0; u < N4A; u++) {
            int idx = t + u * THREADS;
            int r = idx / (BK / 4), c = idx % (BK / 4);
            ra[u] = *(const float4*)(A + (brow + r) * lda + k0 + c * 4);
        }
        #pragma unroll
        for (int u = 0; u < N4B; u++) {
            int idx = t + u * THREADS;
            if constexpr (BTR) {
                int r = idx / (BK / 4), c = idx % (BK / 4);
                rb[u] = *(const float4*)(B + (long long)(bcol + r) * ldb + k0 + c * 4);
            } else {
                int r = idx / (BN / 4), c = idx % (BN / 4);
                rb[u] = *(const float4*)(B + (long long)(k0 + r) * ldb + bcol + c * 4);
            }
        }
    };
    auto stAB = [&](int buf) {
        #pragma unroll
        for (int u = 0; u < N4A; u++) {
            int idx = t + u * THREADS;
            int r = idx / (BK / 4), c = idx % (BK / 4);
            float4 v = ra[u];
            *(float2*)&Asd[buf][c * 4 + 0][2 * r] = make_float2(v.x, v.x);
            *(float2*)&Asd[buf][c * 4 + 1][2 * r] = make_float2(v.y, v.y);
            *(float2*)&Asd[buf][c * 4 + 2][2 * r] = make_float2(v.z, v.z);
            *(float2*)&Asd[buf][c * 4 + 3][2 * r] = make_float2(v.w, v.w);
        }
        #pragma unroll
        for (int u = 0; u < N4B; u++) {
            int idx = t + u * THREADS;
            if constexpr (BTR) {
                int r = idx / (BK / 4), c = idx % (BK / 4);
                Bs[buf][c * 4 + 0][r] = rb[u].x;
                Bs[buf][c * 4 + 1][r] = rb[u].y;
                Bs[buf][c * 4 + 2][r] = rb[u].z;
                Bs[buf][c * 4 + 3][r] = rb[u].w;
            } else {
                int r = idx / (BN / 4), c = idx % (BN / 4);
                *(float4*)&Bs[buf][r][c * 4] = rb[u];
            }
        }
    };

    const int tr = (t / (BN / TN)) * TM;   // row offset (even)
    const int tc = (t % (BN / TN)) * TN;   // col offset (multiple of 4)
    unsigned long long acc[TM][TN / 2] = {};

    ldAB(0);
    stAB(0);
    __syncthreads();

    const int nst = K / BK;
    for (int s = 0; s < nst; s++) {
        const int buf = s & 1;
        if (s + 1 < nst) ldAB((s + 1) * BK);   // prefetch next slab to regs

        #pragma unroll
        for (int kk = 0; kk < BK; kk++) {
            const unsigned long long* Ar =
                (const unsigned long long*)&Asd[buf][kk][0];
            const unsigned long long* Br =
                (const unsigned long long*)&Bs[buf][kk][0];
            unsigned long long a2[TM], b2[TN / 2];
            #pragma unroll
            for (int i = 0; i < TM; i += 2)
                *(ulonglong2*)&a2[i] = *(const ulonglong2*)&Ar[tr + i];
            #pragma unroll
            for (int j = 0; j < TN / 2; j += 2)
                *(ulonglong2*)&b2[j] = *(const ulonglong2*)&Br[tc / 2 + j];
            #pragma unroll
            for (int i = 0; i < TM; i++)
                #pragma unroll
                for (int j = 0; j < TN / 2; j++)
                    ffma2(acc[i][j], a2[i], b2[j]);
        }

        if (s + 1 < nst) stAB(buf ^ 1);        // safe: other buf idle since last sync
        __syncthreads();
    }

    #pragma unroll
    for (int i = 0; i < TM; i++) {
        long long r = brow + tr + i;
        float* Crow = C + r * ldc;
        float rs = 1.f;
        if (EPI == 4) rs = 1.f / (aux[sAux * z + r] + 1e-8f);
        #pragma unroll
        for (int j = 0; j < TN / 2; j++) {
            union { unsigned long long u; float2 f; } cv;
            cv.u = acc[i][j];
            #pragma unroll
            for (int h = 0; h < 2; h++) {
                int cix = bcol + tc + 2 * j + h;
                float v = (h ? cv.f.y : cv.f.x) * alpha;
                if (EPI == 0)      Crow[cix] = v;
                else if (EPI == 1) Crow[cix] = fmaxf(v, 0.f);
                else if (EPI == 2) Crow[cix] = aux[r * (long long)ldAux + cix] / (1.f + expf(-v));
                else if (EPI == 3) Crow[cix] += v;
                else {             // EPI == 4
                    float o = v * rs;
                    Crow[cix] = o;
                    C2[r * ldc + cix] = o;
                }
            }
        }
    }
}

// ---------------------------------------------------------------------------
// Column softmax stats (max & sum of exp over 128 slots per column)
// ---------------------------------------------------------------------------
__global__ __launch_bounds__(128) void colstats_kernel()
{
    int b = blockIdx.y;
    int m = blockIdx.x * 128 + threadIdx.x;
    const float* Lb = g_L + (long long)b * NS * NF;
    float mx = -3.4e38f, s = 0.f;
    for (int n = 0; n < NS; n++) {
        float x = Lb[(long long)n * NF + m];
        if (x > mx) { s = s * expf(mx - x) + 1.f; mx = x; }
        else        { s += expf(x - mx); }
    }
    g_cmax[(long long)b * NF + m] = mx;
    g_csum[(long long)b * NF + m] = s;
}

// ---------------------------------------------------------------------------
// Overwrite logits with probabilities; per-row sums S
// ---------------------------------------------------------------------------
__global__ __launch_bounds__(256) void rowsum_kernel()
{
    __shared__ float red[8];
    int b = blockIdx.y, n = blockIdx.x;
    float* Lr = g_L + ((long long)b * NS + n) * NF;
    const float* cm = g_cmax + (long long)b * NF;
    const float* cs = g_csum + (long long)b * NF;
    float s = 0.f;
    for (int m = threadIdx.x; m < NF; m += 256) {
        float p = expf(Lr[m] - cm[m]) / cs[m];
        Lr[m] = p;
        s += p;
    }
    float tot = block_sum(s, red);
    if (threadIdx.x == 0) g_S[b * NS + n] = tot;
}

// ---------------------------------------------------------------------------
// Host launcher
// ---------------------------------------------------------------------------
extern "C" void kernel_launch(void* const* d_in, const int* in_sizes, int n_in,
                              void* d_out, int out_size)
{
    // Input ordering: reference-signature order (t first, size 1) or
    // setup_inputs order (q_w0 first).
    const bool tfirst = (in_sizes[0] == 1);
    const int iH  = tfirst ? 4  : 0;
    const int iLn = tfirst ? 28 : 24;
    const int iT  = tfirst ? 0  : 28;
    const int iS  = tfirst ? 1  : 29;
    const int iK  = tfirst ? 2  : 30;
    const int iV  = tfirst ? 3  : 31;

    auto F = [&](int i) { return (const float*)d_in[i]; };
    const float* t     = F(iT);
    const float* slots = F(iS);
    const float* kin   = F(iK);
    const float* vin   = F(iV);

    const float *hw0[4], *hb0[4], *hw1[4], *hb1[4], *hwp[4], *hbp[4];
    for (int h = 0; h < 4; h++) {
        int base = iH + h * 6;
        hw0[h] = F(base);     hb0[h] = F(base + 1);
        hw1[h] = F(base + 2); hb1[h] = F(base + 3);
        hwp[h] = F(base + 4); hbp[h] = F(base + 5);
    }

    float *pW, *pcatA, *pcatF, *pq, *pL, *pffh, *pS;
    cudaGetSymbolAddress((void**)&pW,    g_W);
    cudaGetSymbolAddress((void**)&pcatA, g_catA);
    cudaGetSymbolAddress((void**)&pcatF, g_catF);
    cudaGetSymbolAddress((void**)&pq,    g_q);
    cudaGetSymbolAddress((void**)&pL,    g_L);
    cudaGetSymbolAddress((void**)&pffh,  g_ffh);
    cudaGetSymbolAddress((void**)&pS,    g_S);

    float* out = (float*)d_out;

    // 1) time-dependent MLPs
    time_mlp_kernel<<<4, 64>>>(t,
        hw0[0], hb0[0], hw1[0], hb1[0],
        hw0[1], hb0[1], hw1[1], hb1[1],
        hw0[2], hb0[2], hw1[2], hb1[2],
        hw0[3], hb0[3], hw1[3], hb1[3]);

    // 2) W = wp @ h + bp (all 4 heads)
    wproj_kernel<<<3840, 256>>>(hwp[0], hbp[0], hwp[1], hbp[1],
                                hwp[2], hbp[2], hwp[3], hbp[3]);

    // 3) LayerNorm -> catA/catF first halves
    ln_kernel<<<4096, 256>>>(slots, F(iLn), F(iLn + 1), F(iLn + 2), F(iLn + 3));

    // 4) q = lnA(slots) @ Wq^T        [4096,256]
    gemm2<64, 64, 16, 4, 4, 256, true, 0><<<dim3(4, 64, 1), 256>>>(
        pcatA, 512, 0, pW + OFF_WQ, 256, 0, pq, 256, 0,
        256, 1.f, nullptr, 0, 0, nullptr);

    // 5) logits = scale * q @ k^T     per batch [128,4096]
    gemm2<128, 128, 8, 8, 8, 256, true, 0><<<dim3(32, 1, 32), 256>>>(
        pq, 256, (long long)NS * DD,
        kin, 256, (long long)NF * DD,
        pL, NF, (long long)NS * NF,
        256, 0.0625f, nullptr, 0, 0, nullptr);

    // 6) softmax over slots: per-column max & sum
    colstats_kernel<<<dim3(32, 32), 128>>>();

    // 7) probabilities in-place; row sums S
    rowsum_kernel<<<dim3(128, 32), 256>>>();

    // 8) f_attn = (P @ V) / (S+1e-8) -> catA/catF second halves  (NN gemm)
    gemm2<64, 64, 16, 4, 4, 256, false, 4><<<dim3(4, 2, 32), 256>>>(
        pL, NF, (long long)NS * NF,
        vin, DD, (long long)NF * DD,
        pcatA + 256, 512, (long long)NS * 512,
        NF, 1.f, pS, NS, 0, pcatF + 256);

    // 9) out = sigmoid(catA @ Wg^T) * f_attn
    gemm2<64, 64, 16, 4, 4, 256, true, 2><<<dim3(4, 64, 1), 256>>>(
        pcatA, 512, 0, pW + OFF_WG, 512, 0, out, 256, 0,
        512, 1.f, pcatA + 256, 0, 512, nullptr);

    // 10) h = relu(catF @ Wf0^T)      [4096,1024]
    gemm2<128, 128, 8, 8, 8, 256, true, 1><<<dim3(8, 32, 1), 256>>>(
        pcatF, 512, 0, pW + OFF_WF0, 512, 0, pffh, 1024, 0,
        512, 1.f, nullptr, 0, 0, nullptr);

    // 11) out += h @ Wf1^T
    gemm2<64, 64, 16, 4, 4, 256, true, 3><<<dim3(4, 64, 1), 256>>>(
        pffh, 1024, 0, pW + OFF_WF1, 1024, 0, out, 256, 0,
        1024, 1.f, nullptr, 0, 0, nullptr);
}

// round 15
// speedup vs baseline: 1.1323x; 1.1323x over previous
#include <cuda_runtime.h>
#include <cuda_bf16.h>
#include <math.h>
#include <cstdint>

// ---------------------------------------------------------------------------
// Problem constants
// ---------------------------------------------------------------------------
constexpr int BB = 32;      // batch
constexpr int NS = 128;     // slots
constexpr int NF = 4096;    // features
constexpr int DD = 256;     // slot dim
constexpr int HH = 1024;    // mlp hidden

// ---------------------------------------------------------------------------
// Device scratch (static globals: allocation-free, graph-safe)
// ---------------------------------------------------------------------------
__device__ float g_h[4][64];
__device__ float g_W[983040];                      // Wq | Wg | Wf0 | Wf1
__device__ float g_catA[(size_t)BB * NS * 2 * DD]; // [lnA(slots) , f_attn]
__device__ float g_catF[(size_t)BB * NS * 2 * DD]; // [lnF(slots) , f_attn]
__device__ float g_q[(size_t)BB * NS * DD];
__device__ float g_L[(size_t)BB * NS * NF];        // logits -> probabilities
__device__ float g_cmax[(size_t)BB * NF];
__device__ float g_csum[(size_t)BB * NF];
__device__ float g_S[(size_t)BB * NS];
__device__ float g_ffh[(size_t)BB * NS * HH];

constexpr int OFF_WQ  = 0;
constexpr int OFF_WG  = 65536;
constexpr int OFF_WF0 = 196608;
constexpr int OFF_WF1 = 720896;

// ---------------------------------------------------------------------------
// Helpers
// ---------------------------------------------------------------------------
__device__ __forceinline__ float block_sum(float v, float* red) {
    __syncthreads();
    int lane = threadIdx.x & 31, w = threadIdx.x >> 5;
    #pragma unroll
    for (int o = 16; o; o >>= 1) v += __shfl_xor_sync(0xffffffffu, v, o);
    if (lane == 0) red[w] = v;
    __syncthreads();
    float tot = 0.f;
    int nw = (blockDim.x + 31) >> 5;
    for (int i = 0; i < nw; i++) tot += red[i];
    return tot;
}

__device__ __forceinline__ void ldsm_x4(uint32_t* r, uint32_t addr) {
    asm volatile("ldmatrix.sync.aligned.m8n8.x4.shared.b16 {%0,%1,%2,%3}, [%4];"
                 : "=r"(r[0]), "=r"(r[1]), "=r"(r[2]), "=r"(r[3]) : "r"(addr));
}
__device__ __forceinline__ void ldsm_x2(uint32_t* r, uint32_t addr) {
    asm volatile("ldmatrix.sync.aligned.m8n8.x2.shared.b16 {%0,%1}, [%2];"
                 : "=r"(r[0]), "=r"(r[1]) : "r"(addr));
}
__device__ __forceinline__ void mma16816(float* d, const uint32_t* a,
                                         const uint32_t* b) {
    asm volatile(
        "mma.sync.aligned.m16n8k16.row.col.f32.bf16.bf16.f32 "
        "{%0,%1,%2,%3}, {%4,%5,%6,%7}, {%8,%9}, {%0,%1,%2,%3};"
        : "+f"(d[0]), "+f"(d[1]), "+f"(d[2]), "+f"(d[3])
        : "r"(a[0]), "r"(a[1]), "r"(a[2]), "r"(a[3]), "r"(b[0]), "r"(b[1]));
}

// ---------------------------------------------------------------------------
// Tensor-core GEMM via mma.sync, split-bf16 (hi/lo) for ~1e-5 accuracy.
//   BTR=true : C[M,N] = epi(alpha * A[M,K] @ B[N,K]^T)   (both K-contiguous)
//   BTR=false: C[M,N] = epi(alpha * A[M,K] @ B[K,N])     (B N-contig; smem transpose)
// Block tile 128x128, K-chunk 32, 256 threads = 8 warps (2x4), warp tile 64x32.
// EPI: 0 store | 1 relu | 2 aux*sigmoid(v) | 3 C+=v | 4 v/(aux[row]+1e-8)->C,C2
// ---------------------------------------------------------------------------
constexpr int ST = 40;   // smem row stride in bf16 (conflict-free ldmatrix)

template<bool BTR, int EPI>
__global__ __launch_bounds__(256) void mma_tn(
    const float* __restrict__ A, int lda, long long sA,
    const float* __restrict__ B, int ldb, long long sB,
    float* __restrict__ C, int ldc, long long sC,
    int K, float alpha,
    const float* __restrict__ aux, long long sAux, int ldAux,
    float* __restrict__ C2)
{
    __shared__ __align__(16) __nv_bfloat16 Ahi[128 * ST], Alo[128 * ST];
    __shared__ __align__(16) __nv_bfloat16 Bhi[128 * ST], Blo[128 * ST];

    const int tid = threadIdx.x;
    const int lane = tid & 31, wid = tid >> 5;
    const int wm = wid >> 2, wn = wid & 3;          // 2 x 4 warp grid
    const int z = blockIdx.z;
    A += sA * z; B += sB * z; C += sC * z;
    if (EPI == 4 && C2) C2 += sC * z;

    const long long brow = (long long)blockIdx.y * 128;
    const int bcol = blockIdx.x * 128;

    const uint32_t bAhi = (uint32_t)__cvta_generic_to_shared(Ahi);
    const uint32_t bAlo = (uint32_t)__cvta_generic_to_shared(Alo);
    const uint32_t bBhi = (uint32_t)__cvta_generic_to_shared(Bhi);
    const uint32_t bBlo = (uint32_t)__cvta_generic_to_shared(Blo);

    float acc[4][4][4] = {};     // [mi][ni][frag]

    // fragment smem addresses (constant across chunks except kk offset)
    const int rowa = wm * 64 + (lane & 15);
    const int cola_off = ((lane >> 4) & 1) * 8;
    const int rowb = wn * 32 + (lane & 7);
    const int colb_off = ((lane >> 3) & 1) * 8;

    const int nchunks = K / 32;
    for (int c = 0; c < nchunks; c++) {
        const int k0 = c * 32;
        __syncthreads();                       // smem free (prev compute done)

        // ---- load + convert A chunk: rows brow..+127, k0..k0+31
        for (int idx = tid; idx < 128 * 32; idx += 256) {
            int r = idx >> 5, cc = idx & 31;
            float f = A[(brow + r) * lda + k0 + cc];
            __nv_bfloat16 h = __float2bfloat16(f);
            Ahi[r * ST + cc] = h;
            Alo[r * ST + cc] = __float2bfloat16(f - __bfloat162float(h));
        }
        // ---- load + convert B chunk
        if (BTR) {
            for (int idx = tid; idx < 128 * 32; idx += 256) {
                int r = idx >> 5, cc = idx & 31;
                float f = B[(long long)(bcol + r) * ldb + k0 + cc];
                __nv_bfloat16 h = __float2bfloat16(f);
                Bhi[r * ST + cc] = h;
                Blo[r * ST + cc] = __float2bfloat16(f - __bfloat162float(h));
            }
        } else {
            for (int idx = tid; idx < 128 * 32; idx += 256) {
                int k = idx >> 7, n = idx & 127;    // coalesced gmem read
                float f = B[(long long)(k0 + k) * ldb + bcol + n];
                __nv_bfloat16 h = __float2bfloat16(f);
                Bhi[n * ST + k] = h;                // transpose in smem
                Blo[n * ST + k] = __float2bfloat16(f - __bfloat162float(h));
            }
        }
        __syncthreads();

        // ---- tensor-core compute on this chunk
        #pragma unroll
        for (int kk = 0; kk < 32; kk += 16) {
            uint32_t ahi[4][4], alo[4][4], bhi[4][2], blo[4][2];
            #pragma unroll
            for (int mi = 0; mi < 4; mi++) {
                uint32_t off = (uint32_t)(((rowa + mi * 16) * ST + kk + cola_off) * 2);
                ldsm_x4(ahi[mi], bAhi + off);
                ldsm_x4(alo[mi], bAlo + off);
            }
            #pragma unroll
            for (int ni = 0; ni < 4; ni++) {
                uint32_t off = (uint32_t)(((rowb + ni * 8) * ST + kk + colb_off) * 2);
                ldsm_x2(bhi[ni], bBhi + off);
                ldsm_x2(blo[ni], bBlo + off);
            }
            #pragma unroll
            for (int mi = 0; mi < 4; mi++)
                #pragma unroll
                for (int ni = 0; ni < 4; ni++)
                    mma16816(acc[mi][ni], ahi[mi], bhi[ni]);
            #pragma unroll
            for (int mi = 0; mi < 4; mi++)
                #pragma unroll
                for (int ni = 0; ni < 4; ni++)
                    mma16816(acc[mi][ni], ahi[mi], blo[ni]);
            #pragma unroll
            for (int mi = 0; mi < 4; mi++)
                #pragma unroll
                for (int ni = 0; ni < 4; ni++)
                    mma16816(acc[mi][ni], alo[mi], bhi[ni]);
        }
    }

    // ---- epilogue: c-frag lane mapping: rows l/4 & l/4+8, cols 2*(l%4)+{0,1}
    #pragma unroll
    for (int mi = 0; mi < 4; mi++) {
        #pragma unroll
        for (int ni = 0; ni < 4; ni++) {
            long long r0 = brow + wm * 64 + mi * 16 + (lane >> 2);
            int cn = bcol + wn * 32 + ni * 8 + (lane & 3) * 2;
            #pragma unroll
            for (int half = 0; half < 2; half++) {
                long long r = r0 + half * 8;
                float v0 = acc[mi][ni][half * 2 + 0] * alpha;
                float v1 = acc[mi][ni][half * 2 + 1] * alpha;
                float* Cp = C + r * ldc + cn;
                if (EPI == 0) {
                    Cp[0] = v0; Cp[1] = v1;
                } else if (EPI == 1) {
                    Cp[0] = fmaxf(v0, 0.f); Cp[1] = fmaxf(v1, 0.f);
                } else if (EPI == 2) {
                    const float* ax = aux + r * (long long)ldAux + cn;
                    Cp[0] = ax[0] / (1.f + expf(-v0));
                    Cp[1] = ax[1] / (1.f + expf(-v1));
                } else if (EPI == 3) {
                    Cp[0] += v0; Cp[1] += v1;
                } else {   // EPI == 4
                    float rs = 1.f / (aux[sAux * z + r] + 1e-8f);
                    float o0 = v0 * rs, o1 = v1 * rs;
                    Cp[0] = o0; Cp[1] = o1;
                    float* C2p = C2 + r * ldc + cn;
                    C2p[0] = o0; C2p[1] = o1;
                }
            }
        }
    }
}

// ---------------------------------------------------------------------------
// Kernel 1: sinusoidal embedding + 2-layer SiLU MLP for all 4 heads
// ---------------------------------------------------------------------------
__global__ void time_mlp_kernel(
    const float* __restrict__ t_ptr,
    const float* qw0, const float* qb0, const float* qw1, const float* qb1,
    const float* gw0, const float* gb0, const float* gw1, const float* gb1,
    const float* f0w0, const float* f0b0, const float* f0w1, const float* f0b1,
    const float* f1w0, const float* f1b0, const float* f1w1, const float* f1b1)
{
    const float* w0s[4] = {qw0, gw0, f0w0, f1w0};
    const float* b0s[4] = {qb0, gb0, f0b0, f1b0};
    const float* w1s[4] = {qw1, gw1, f0w1, f1w1};
    const float* b1s[4] = {qb1, gb1, f0b1, f1b1};
    int head = blockIdx.x;
    const float* w0 = w0s[head]; const float* b0 = b0s[head];
    const float* w1 = w1s[head]; const float* b1 = b1s[head];

    __shared__ float emb[257];
    __shared__ float h0[64];
    int tid = threadIdx.x;
    float t = t_ptr[0];
    if (tid == 0) emb[0] = t;
    const float fscale = -logf(10000.0f) / 128.0f;
    for (int i = tid; i < 128; i += 64) {
        float w = fscale * (float)i * t;
        emb[1 + i]   = sinf(w);
        emb[129 + i] = cosf(w);
    }
    __syncthreads();
    float s = b0[tid];
    for (int j = 0; j < 257; j++) s += w0[tid * 257 + j] * emb[j];
    h0[tid] = s / (1.f + expf(-s));
    __syncthreads();
    float s2 = b1[tid];
    #pragma unroll 8
    for (int j = 0; j < 64; j++) s2 += w1[tid * 64 + j] * h0[j];
    g_h[head][tid] = s2 / (1.f + expf(-s2));
}

// ---------------------------------------------------------------------------
// Kernel 2: W = wp @ h + bp for all heads (983040 rows x 64) -> g_W
// ---------------------------------------------------------------------------
__global__ __launch_bounds__(256) void wproj_kernel(
    const float* __restrict__ qwp,  const float* __restrict__ qbp,
    const float* __restrict__ gwp,  const float* __restrict__ gbp,
    const float* __restrict__ f0wp, const float* __restrict__ f0bp,
    const float* __restrict__ f1wp, const float* __restrict__ f1bp)
{
    long long r = (long long)blockIdx.x * 256 + threadIdx.x;
    int head; const float* wp; const float* bp; long long lr;
    if (r < 65536)       { head = 0; wp = qwp;  bp = qbp;  lr = r; }
    else if (r < 196608) { head = 1; wp = gwp;  bp = gbp;  lr = r - 65536; }
    else if (r < 720896) { head = 2; wp = f0wp; bp = f0bp; lr = r - 196608; }
    else                 { head = 3; wp = f1wp; bp = f1bp; lr = r - 720896; }

    __shared__ float hs[64];
    if (threadIdx.x < 64) hs[threadIdx.x] = g_h[head][threadIdx.x];
    __syncthreads();

    const float4* w4 = (const float4*)(wp + lr * 64);
    float s = bp[lr];
    #pragma unroll
    for (int j = 0; j < 16; j++) {
        float4 x = w4[j];
        s += x.x * hs[4 * j] + x.y * hs[4 * j + 1] + x.z * hs[4 * j + 2] + x.w * hs[4 * j + 3];
    }
    g_W[r] = s;
}

// ---------------------------------------------------------------------------
// Kernel 3: LayerNorm -> first halves of g_catA / g_catF
// ---------------------------------------------------------------------------
__global__ __launch_bounds__(256) void ln_kernel(
    const float* __restrict__ slots,
    const float* __restrict__ aw, const float* __restrict__ ab,
    const float* __restrict__ fw, const float* __restrict__ fb)
{
    __shared__ float red[8];
    long long row = blockIdx.x;
    int d = threadIdx.x;
    float x = slots[row * 256 + d];
    float mu  = block_sum(x, red) * (1.f / 256.f);
    float dv  = x - mu;
    float var = block_sum(dv * dv, red) * (1.f / 256.f);
    float xh  = dv * rsqrtf(var + 1e-5f);
    g_catA[row * 512 + d] = xh * aw[d] + ab[d];
    g_catF[row * 512 + d] = xh * fw[d] + fb[d];
}

// ---------------------------------------------------------------------------
// Column softmax stats (max & sum of exp over 128 slots per column)
// ---------------------------------------------------------------------------
__global__ __launch_bounds__(128) void colstats_kernel()
{
    int b = blockIdx.y;
    int m = blockIdx.x * 128 + threadIdx.x;
    const float* Lb = g_L + (long long)b * NS * NF;
    float mx = -3.4e38f, s = 0.f;
    for (int n = 0; n < NS; n++) {
        float x = Lb[(long long)n * NF + m];
        if (x > mx) { s = s * expf(mx - x) + 1.f; mx = x; }
        else        { s += expf(x - mx); }
    }
    g_cmax[(long long)b * NF + m] = mx;
    g_csum[(long long)b * NF + m] = s;
}

// ---------------------------------------------------------------------------
// Probabilities in-place; per-row sums S
// ---------------------------------------------------------------------------
__global__ __launch_bounds__(256) void rowsum_kernel()
{
    __shared__ float red[8];
    int b = blockIdx.y, n = blockIdx.x;
    float* Lr = g_L + ((long long)b * NS + n) * NF;
    const float* cm = g_cmax + (long long)b * NF;
    const float* cs = g_csum + (long long)b * NF;
    float s = 0.f;
    for (int m = threadIdx.x; m < NF; m += 256) {
        float p = expf(Lr[m] - cm[m]) / cs[m];
        Lr[m] = p;
        s += p;
    }
    float tot = block_sum(s, red);
    if (threadIdx.x == 0) g_S[b * NS + n] = tot;
}

// ---------------------------------------------------------------------------
// Host launcher
// ---------------------------------------------------------------------------
extern "C" void kernel_launch(void* const* d_in, const int* in_sizes, int n_in,
                              void* d_out, int out_size)
{
    const bool tfirst = (in_sizes[0] == 1);
    const int iH  = tfirst ? 4  : 0;
    const int iLn = tfirst ? 28 : 24;
    const int iT  = tfirst ? 0  : 28;
    const int iS  = tfirst ? 1  : 29;
    const int iK  = tfirst ? 2  : 30;
    const int iV  = tfirst ? 3  : 31;

    auto F = [&](int i) { return (const float*)d_in[i]; };
    const float* t     = F(iT);
    const float* slots = F(iS);
    const float* kin   = F(iK);
    const float* vin   = F(iV);

    const float *hw0[4], *hb0[4], *hw1[4], *hb1[4], *hwp[4], *hbp[4];
    for (int h = 0; h < 4; h++) {
        int base = iH + h * 6;
        hw0[h] = F(base);     hb0[h] = F(base + 1);
        hw1[h] = F(base + 2); hb1[h] = F(base + 3);
        hwp[h] = F(base + 4); hbp[h] = F(base + 5);
    }

    float *pW, *pcatA, *pcatF, *pq, *pL, *pffh, *pS;
    cudaGetSymbolAddress((void**)&pW,    g_W);
    cudaGetSymbolAddress((void**)&pcatA, g_catA);
    cudaGetSymbolAddress((void**)&pcatF, g_catF);
    cudaGetSymbolAddress((void**)&pq,    g_q);
    cudaGetSymbolAddress((void**)&pL,    g_L);
    cudaGetSymbolAddress((void**)&pffh,  g_ffh);
    cudaGetSymbolAddress((void**)&pS,    g_S);

    float* out = (float*)d_out;

    // 1) time-dependent MLPs
    time_mlp_kernel<<<4, 64>>>(t,
        hw0[0], hb0[0], hw1[0], hb1[0],
        hw0[1], hb0[1], hw1[1], hb1[1],
        hw0[2], hb0[2], hw1[2], hb1[2],
        hw0[3], hb0[3], hw1[3], hb1[3]);

    // 2) W = wp @ h + bp (all 4 heads)
    wproj_kernel<<<3840, 256>>>(hwp[0], hbp[0], hwp[1], hbp[1],
                                hwp[2], hbp[2], hwp[3], hbp[3]);

    // 3) LayerNorm -> catA/catF first halves
    ln_kernel<<<4096, 256>>>(slots, F(iLn), F(iLn + 1), F(iLn + 2), F(iLn + 3));

    // 4) q = lnA(slots) @ Wq^T      [4096,256], K=256
    mma_tn<true, 0><<<dim3(2, 32, 1), 256>>>(
        pcatA, 512, 0, pW + OFF_WQ, 256, 0, pq, 256, 0,
        256, 1.f, nullptr, 0, 0, nullptr);

    // 5) logits = scale * q @ k^T   per batch [128,4096], K=256
    mma_tn<true, 0><<<dim3(32, 1, 32), 256>>>(
        pq, 256, (long long)NS * DD,
        kin, 256, (long long)NF * DD,
        pL, NF, (long long)NS * NF,
        256, 0.0625f, nullptr, 0, 0, nullptr);

    // 6) softmax over slots: per-column max & sum
    colstats_kernel<<<dim3(32, 32), 128>>>();

    // 7) probabilities in-place; row sums S
    rowsum_kernel<<<dim3(128, 32), 256>>>();

    // 8) f_attn = (P @ V) / (S+1e-8) -> catA/catF second halves  (NN form)
    mma_tn<false, 4><<<dim3(2, 1, 32), 256>>>(
        pL, NF, (long long)NS * NF,
        vin, DD, (long long)NF * DD,
        pcatA + 256, 512, (long long)NS * 512,
        NF, 1.f, pS, NS, 0, pcatF + 256);

    // 9) out = sigmoid(catA @ Wg^T) * f_attn   [4096,256], K=512
    mma_tn<true, 2><<<dim3(2, 32, 1), 256>>>(
        pcatA, 512, 0, pW + OFF_WG, 512, 0, out, 256, 0,
        512, 1.f, pcatA + 256, 0, 512, nullptr);

    // 10) h = relu(catF @ Wf0^T)    [4096,1024], K=512
    mma_tn<true, 1><<<dim3(8, 32, 1), 256>>>(
        pcatF, 512, 0, pW + OFF_WF0, 512, 0, pffh, 1024, 0,
        512, 1.f, nullptr, 0, 0, nullptr);

    // 11) out += h @ Wf1^T          [4096,256], K=1024
    mma_tn<true, 3><<<dim3(2, 32, 1), 256>>>(
        pffh, 1024, 0, pW + OFF_WF1, 1024, 0, out, 256, 0,
        1024, 1.f, nullptr, 0, 0, nullptr);
}

// round 16
// speedup vs baseline: 2.0105x; 1.7755x over previous
#include <cuda_runtime.h>
#include <cuda_bf16.h>
#include <math.h>
#include <cstdint>

// ---------------------------------------------------------------------------
// Problem constants
// ---------------------------------------------------------------------------
constexpr int BB = 32;      // batch
constexpr int NS = 128;     // slots
constexpr int NF = 4096;    // features
constexpr int DD = 256;     // slot dim
constexpr int HH = 1024;    // mlp hidden

// ---------------------------------------------------------------------------
// Device scratch (static globals: allocation-free, graph-safe)
// ---------------------------------------------------------------------------
__device__ float g_h[4][64];
__device__ float g_W[983040];                      // Wq | Wg | Wf0 | Wf1
__device__ float g_catA[(size_t)BB * NS * 2 * DD]; // [lnA(slots) , f_attn]
__device__ float g_catF[(size_t)BB * NS * 2 * DD]; // [lnF(slots) , f_attn]
__device__ float g_q[(size_t)BB * NS * DD];
__device__ float g_L[(size_t)BB * NS * NF];        // logits -> probabilities
__device__ float g_cmax[(size_t)BB * NF];
__device__ float g_csum[(size_t)BB * NF];
__device__ float g_S[(size_t)BB * NS];
__device__ float g_ffh[(size_t)BB * NS * HH];

constexpr int OFF_WQ  = 0;
constexpr int OFF_WG  = 65536;
constexpr int OFF_WF0 = 196608;
constexpr int OFF_WF1 = 720896;

// ---------------------------------------------------------------------------
// Helpers
// ---------------------------------------------------------------------------
__device__ __forceinline__ float block_sum(float v, float* red) {
    __syncthreads();
    int lane = threadIdx.x & 31, w = threadIdx.x >> 5;
    #pragma unroll
    for (int o = 16; o; o >>= 1) v += __shfl_xor_sync(0xffffffffu, v, o);
    if (lane == 0) red[w] = v;
    __syncthreads();
    float tot = 0.f;
    int nw = (blockDim.x + 31) >> 5;
    for (int i = 0; i < nw; i++) tot += red[i];
    return tot;
}

__device__ __forceinline__ void ldsm_x4(uint32_t* r, uint32_t addr) {
    asm volatile("ldmatrix.sync.aligned.m8n8.x4.shared.b16 {%0,%1,%2,%3}, [%4];"
                 : "=r"(r[0]), "=r"(r[1]), "=r"(r[2]), "=r"(r[3]) : "r"(addr));
}
__device__ __forceinline__ void ldsm_x2(uint32_t* r, uint32_t addr) {
    asm volatile("ldmatrix.sync.aligned.m8n8.x2.shared.b16 {%0,%1}, [%2];"
                 : "=r"(r[0]), "=r"(r[1]) : "r"(addr));
}
__device__ __forceinline__ void mma16816(float* d, const uint32_t* a,
                                         const uint32_t* b) {
    asm volatile(
        "mma.sync.aligned.m16n8k16.row.col.f32.bf16.bf16.f32 "
        "{%0,%1,%2,%3}, {%4,%5,%6,%7}, {%8,%9}, {%0,%1,%2,%3};"
        : "+f"(d[0]), "+f"(d[1]), "+f"(d[2]), "+f"(d[3])
        : "r"(a[0]), "r"(a[1]), "r"(a[2]), "r"(a[3]), "r"(b[0]), "r"(b[1]));
}

// ---------------------------------------------------------------------------
// Tensor-core GEMM via mma.sync, split-bf16 (hi/lo), double-buffered with
// register prefetch (1 sync per 32-K chunk).
//   BTR=true : C[M,N] = epi(alpha * A[M,K] @ B[N,K]^T)   (both K-contiguous)
//   BTR=false: C[M,N] = epi(alpha * A[M,K] @ B[K,N])     (B N-contig; smem transpose)
// Block tile BM x BN, warp grid WM x WN (THREADS = WM*WN*32).
// EPI: 0 store | 1 relu | 2 aux*sigmoid(v) | 3 C+=v | 4 v/(aux[row]+1e-8)->C,C2
// Dynamic smem: 8*ST*(BM+BN) bytes.
// ---------------------------------------------------------------------------
constexpr int ST = 40;   // smem row stride in bf16 (conflict-free ldmatrix)

template<int BM, int BN, int WM, int WN, bool BTR, int EPI>
__global__ __launch_bounds__(WM * WN * 32) void mma_tn(
    const float* __restrict__ A, int lda, long long sA,
    const float* __restrict__ B, int ldb, long long sB,
    float* __restrict__ C, int ldc, long long sC,
    int K, float alpha,
    const float* __restrict__ aux, long long sAux, int ldAux,
    float* __restrict__ C2)
{
    constexpr int THREADS = WM * WN * 32;
    constexpr int WTM = BM / WM, WTN = BN / WN;
    constexpr int MI = WTM / 16, NI = WTN / 8;
    constexpr int NA = (BM * 8) / THREADS;   // float4 per thread for A chunk
    constexpr int NB = (BN * 8) / THREADS;
    static_assert(NA >= 1 && NB >= 1, "tile/thread mismatch");

    extern __shared__ __align__(16) char dynsm[];
    __nv_bfloat16* Ahi = (__nv_bfloat16*)dynsm;       // [2][BM*ST]
    __nv_bfloat16* Alo = Ahi + 2 * BM * ST;
    __nv_bfloat16* Bhi = Alo + 2 * BM * ST;           // [2][BN*ST]
    __nv_bfloat16* Blo = Bhi + 2 * BN * ST;

    const int tid = threadIdx.x;
    const int lane = tid & 31, wid = tid >> 5;
    const int wm = wid / WN, wn = wid % WN;
    const int z = blockIdx.z;
    A += sA * z; B += sB * z; C += sC * z;
    if (EPI == 4 && C2) C2 += sC * z;

    const long long brow = (long long)blockIdx.y * BM;
    const int bcol = blockIdx.x * BN;

    const uint32_t bAhi = (uint32_t)__cvta_generic_to_shared(Ahi);
    const uint32_t bAlo = (uint32_t)__cvta_generic_to_shared(Alo);
    const uint32_t bBhi = (uint32_t)__cvta_generic_to_shared(Bhi);
    const uint32_t bBlo = (uint32_t)__cvta_generic_to_shared(Blo);

    float4 ra[NA], rb[NB];

    auto ldAB = [&](int k0) {
        #pragma unroll
        for (int u = 0; u < NA; u++) {
            int idx = tid + u * THREADS;
            int r = idx >> 3, c4 = (idx & 7) * 4;
            ra[u] = *(const float4*)(A + (brow + r) * lda + k0 + c4);
        }
        #pragma unroll
        for (int u = 0; u < NB; u++) {
            int idx = tid + u * THREADS;
            if constexpr (BTR) {
                int r = idx >> 3, c4 = (idx & 7) * 4;
                rb[u] = *(const float4*)(B + (long long)(bcol + r) * ldb + k0 + c4);
            } else {
                int k = idx / (BN / 4), c4 = (idx % (BN / 4)) * 4;
                rb[u] = *(const float4*)(B + (long long)(k0 + k) * ldb + bcol + c4);
            }
        }
    };
    auto cvst = [&](int buf) {
        __nv_bfloat16* ah = Ahi + buf * (BM * ST);
        __nv_bfloat16* al = Alo + buf * (BM * ST);
        __nv_bfloat16* bh = Bhi + buf * (BN * ST);
        __nv_bfloat16* bl = Blo + buf * (BN * ST);
        #pragma unroll
        for (int u = 0; u < NA; u++) {
            int idx = tid + u * THREADS;
            int r = idx >> 3, c4 = (idx & 7) * 4;
            const float* f = (const float*)&ra[u];
            #pragma unroll
            for (int e = 0; e < 4; e++) {
                __nv_bfloat16 h = __float2bfloat16(f[e]);
                ah[r * ST + c4 + e] = h;
                al[r * ST + c4 + e] = __float2bfloat16(f[e] - __bfloat162float(h));
            }
        }
        #pragma unroll
        for (int u = 0; u < NB; u++) {
            int idx = tid + u * THREADS;
            const float* f = (const float*)&rb[u];
            if constexpr (BTR) {
                int r = idx >> 3, c4 = (idx & 7) * 4;
                #pragma unroll
                for (int e = 0; e < 4; e++) {
                    __nv_bfloat16 h = __float2bfloat16(f[e]);
                    bh[r * ST + c4 + e] = h;
                    bl[r * ST + c4 + e] = __float2bfloat16(f[e] - __bfloat162float(h));
                }
            } else {
                int k = idx / (BN / 4), c4 = (idx % (BN / 4)) * 4;
                #pragma unroll
                for (int e = 0; e < 4; e++) {     // transpose in smem
                    __nv_bfloat16 h = __float2bfloat16(f[e]);
                    bh[(c4 + e) * ST + k] = h;
                    bl[(c4 + e) * ST + k] = __float2bfloat16(f[e] - __bfloat162float(h));
                }
            }
        }
    };

    const int rowa = wm * WTM + (lane & 15);
    const int cola = ((lane >> 4) & 1) * 8;
    const int rowb = wn * WTN + (lane & 7);
    const int colb = ((lane >> 3) & 1) * 8;

    float acc[MI][NI][4] = {};

    auto compute = [&](int buf) {
        const uint32_t aof = (uint32_t)(buf * BM * ST * 2);
        const uint32_t bof = (uint32_t)(buf * BN * ST * 2);
        #pragma unroll
        for (int kk = 0; kk < 32; kk += 16) {
            uint32_t ahi[MI][4], alo[MI][4], bhi[NI][2], blo[NI][2];
            #pragma unroll
            for (int mi = 0; mi < MI; mi++) {
                uint32_t off = (uint32_t)(((rowa + mi * 16) * ST + kk + cola) * 2);
                ldsm_x4(ahi[mi], bAhi + aof + off);
                ldsm_x4(alo[mi], bAlo + aof + off);
            }
            #pragma unroll
            for (int ni = 0; ni < NI; ni++) {
                uint32_t off = (uint32_t)(((rowb + ni * 8) * ST + kk + colb) * 2);
                ldsm_x2(bhi[ni], bBhi + bof + off);
                ldsm_x2(blo[ni], bBlo + bof + off);
            }
            #pragma unroll
            for (int mi = 0; mi < MI; mi++)
                #pragma unroll
                for (int ni = 0; ni < NI; ni++)
                    mma16816(acc[mi][ni], ahi[mi], bhi[ni]);
            #pragma unroll
            for (int mi = 0; mi < MI; mi++)
                #pragma unroll
                for (int ni = 0; ni < NI; ni++)
                    mma16816(acc[mi][ni], ahi[mi], blo[ni]);
            #pragma unroll
            for (int mi = 0; mi < MI; mi++)
                #pragma unroll
                for (int ni = 0; ni < NI; ni++)
                    mma16816(acc[mi][ni], alo[mi], bhi[ni]);
        }
    };

    ldAB(0);
    cvst(0);
    __syncthreads();

    const int nch = K / 32;
    for (int c = 0; c < nch; c++) {
        if (c + 1 < nch) ldAB((c + 1) * 32);   // prefetch next chunk to regs
        compute(c & 1);
        if (c + 1 < nch) cvst((c + 1) & 1);    // other buffer idle since sync
        __syncthreads();
    }

    // ---- epilogue: rows l/4 & l/4+8, cols 2*(l%4)+{0,1}
    #pragma unroll
    for (int mi = 0; mi < MI; mi++) {
        #pragma unroll
        for (int ni = 0; ni < NI; ni++) {
            long long r0 = brow + wm * WTM + mi * 16 + (lane >> 2);
            int cn = bcol + wn * WTN + ni * 8 + (lane & 3) * 2;
            #pragma unroll
            for (int half = 0; half < 2; half++) {
                long long r = r0 + half * 8;
                float v0 = acc[mi][ni][half * 2 + 0] * alpha;
                float v1 = acc[mi][ni][half * 2 + 1] * alpha;
                float* Cp = C + r * ldc + cn;
                if (EPI == 0) {
                    Cp[0] = v0; Cp[1] = v1;
                } else if (EPI == 1) {
                    Cp[0] = fmaxf(v0, 0.f); Cp[1] = fmaxf(v1, 0.f);
                } else if (EPI == 2) {
                    const float* ax = aux + r * (long long)ldAux + cn;
                    Cp[0] = ax[0] / (1.f + expf(-v0));
                    Cp[1] = ax[1] / (1.f + expf(-v1));
                } else if (EPI == 3) {
                    Cp[0] += v0; Cp[1] += v1;
                } else {   // EPI == 4
                    float rs = 1.f / (aux[sAux * z + r] + 1e-8f);
                    float o0 = v0 * rs, o1 = v1 * rs;
                    Cp[0] = o0; Cp[1] = o1;
                    float* C2p = C2 + r * ldc + cn;
                    C2p[0] = o0; C2p[1] = o1;
                }
            }
        }
    }
}

// ---------------------------------------------------------------------------
// Kernel 1: sinusoidal embedding + 2-layer SiLU MLP for all 4 heads
// ---------------------------------------------------------------------------
__global__ void time_mlp_kernel(
    const float* __restrict__ t_ptr,
    const float* qw0, const float* qb0, const float* qw1, const float* qb1,
    const float* gw0, const float* gb0, const float* gw1, const float* gb1,
    const float* f0w0, const float* f0b0, const float* f0w1, const float* f0b1,
    const float* f1w0, const float* f1b0, const float* f1w1, const float* f1b1)
{
    const float* w0s[4] = {qw0, gw0, f0w0, f1w0};
    const float* b0s[4] = {qb0, gb0, f0b0, f1b0};
    const float* w1s[4] = {qw1, gw1, f0w1, f1w1};
    const float* b1s[4] = {qb1, gb1, f0b1, f1b1};
    int head = blockIdx.x;
    const float* w0 = w0s[head]; const float* b0 = b0s[head];
    const float* w1 = w1s[head]; const float* b1 = b1s[head];

    __shared__ float emb[257];
    __shared__ float h0[64];
    int tid = threadIdx.x;
    float t = t_ptr[0];
    if (tid == 0) emb[0] = t;
    const float fscale = -logf(10000.0f) / 128.0f;
    for (int i = tid; i < 128; i += 64) {
        float w = fscale * (float)i * t;
        emb[1 + i]   = sinf(w);
        emb[129 + i] = cosf(w);
    }
    __syncthreads();
    float s = b0[tid];
    for (int j = 0; j < 257; j++) s += w0[tid * 257 + j] * emb[j];
    h0[tid] = s / (1.f + expf(-s));
    __syncthreads();
    float s2 = b1[tid];
    #pragma unroll 8
    for (int j = 0; j < 64; j++) s2 += w1[tid * 64 + j] * h0[j];
    g_h[head][tid] = s2 / (1.f + expf(-s2));
}

// ---------------------------------------------------------------------------
// Kernel 2: W = wp @ h + bp for all heads (983040 rows x 64) -> g_W
// ---------------------------------------------------------------------------
__global__ __launch_bounds__(256) void wproj_kernel(
    const float* __restrict__ qwp,  const float* __restrict__ qbp,
    const float* __restrict__ gwp,  const float* __restrict__ gbp,
    const float* __restrict__ f0wp, const float* __restrict__ f0bp,
    const float* __restrict__ f1wp, const float* __restrict__ f1bp)
{
    long long r = (long long)blockIdx.x * 256 + threadIdx.x;
    int head; const float* wp; const float* bp; long long lr;
    if (r < 65536)       { head = 0; wp = qwp;  bp = qbp;  lr = r; }
    else if (r < 196608) { head = 1; wp = gwp;  bp = gbp;  lr = r - 65536; }
    else if (r < 720896) { head = 2; wp = f0wp; bp = f0bp; lr = r - 196608; }
    else                 { head = 3; wp = f1wp; bp = f1bp; lr = r - 720896; }

    __shared__ float hs[64];
    if (threadIdx.x < 64) hs[threadIdx.x] = g_h[head][threadIdx.x];
    __syncthreads();

    const float4* w4 = (const float4*)(wp + lr * 64);
    float s = bp[lr];
    #pragma unroll
    for (int j = 0; j < 16; j++) {
        float4 x = w4[j];
        s += x.x * hs[4 * j] + x.y * hs[4 * j + 1] + x.z * hs[4 * j + 2] + x.w * hs[4 * j + 3];
    }
    g_W[r] = s;
}

// ---------------------------------------------------------------------------
// Kernel 3: LayerNorm -> first halves of g_catA / g_catF
// ---------------------------------------------------------------------------
__global__ __launch_bounds__(256) void ln_kernel(
    const float* __restrict__ slots,
    const float* __restrict__ aw, const float* __restrict__ ab,
    const float* __restrict__ fw, const float* __restrict__ fb)
{
    __shared__ float red[8];
    long long row = blockIdx.x;
    int d = threadIdx.x;
    float x = slots[row * 256 + d];
    float mu  = block_sum(x, red) * (1.f / 256.f);
    float dv  = x - mu;
    float var = block_sum(dv * dv, red) * (1.f / 256.f);
    float xh  = dv * rsqrtf(var + 1e-5f);
    g_catA[row * 512 + d] = xh * aw[d] + ab[d];
    g_catF[row * 512 + d] = xh * fw[d] + fb[d];
}

// ---------------------------------------------------------------------------
// Column softmax stats (max & sum of exp over 128 slots per column)
// ---------------------------------------------------------------------------
__global__ __launch_bounds__(128) void colstats_kernel()
{
    int b = blockIdx.y;
    int m = blockIdx.x * 128 + threadIdx.x;
    const float* Lb = g_L + (long long)b * NS * NF;
    float mx = -3.4e38f, s = 0.f;
    for (int n = 0; n < NS; n++) {
        float x = Lb[(long long)n * NF + m];
        if (x > mx) { s = s * expf(mx - x) + 1.f; mx = x; }
        else        { s += expf(x - mx); }
    }
    g_cmax[(long long)b * NF + m] = mx;
    g_csum[(long long)b * NF + m] = s;
}

// ---------------------------------------------------------------------------
// Probabilities in-place; per-row sums S
// ---------------------------------------------------------------------------
__global__ __launch_bounds__(256) void rowsum_kernel()
{
    __shared__ float red[8];
    int b = blockIdx.y, n = blockIdx.x;
    float* Lr = g_L + ((long long)b * NS + n) * NF;
    const float* cm = g_cmax + (long long)b * NF;
    const float* cs = g_csum + (long long)b * NF;
    float s = 0.f;
    for (int m = threadIdx.x; m < NF; m += 256) {
        float p = expf(Lr[m] - cm[m]) / cs[m];
        Lr[m] = p;
        s += p;
    }
    float tot = block_sum(s, red);
    if (threadIdx.x == 0) g_S[b * NS + n] = tot;
}

// ---------------------------------------------------------------------------
// Host launcher
// ---------------------------------------------------------------------------
extern "C" void kernel_launch(void* const* d_in, const int* in_sizes, int n_in,
                              void* d_out, int out_size)
{
    const bool tfirst = (in_sizes[0] == 1);
    const int iH  = tfirst ? 4  : 0;
    const int iLn = tfirst ? 28 : 24;
    const int iT  = tfirst ? 0  : 28;
    const int iS  = tfirst ? 1  : 29;
    const int iK  = tfirst ? 2  : 30;
    const int iV  = tfirst ? 3  : 31;

    auto F = [&](int i) { return (const float*)d_in[i]; };
    const float* t     = F(iT);
    const float* slots = F(iS);
    const float* kin   = F(iK);
    const float* vin   = F(iV);

    const float *hw0[4], *hb0[4], *hw1[4], *hb1[4], *hwp[4], *hbp[4];
    for (int h = 0; h < 4; h++) {
        int base = iH + h * 6;
        hw0[h] = F(base);     hb0[h] = F(base + 1);
        hw1[h] = F(base + 2); hb1[h] = F(base + 3);
        hwp[h] = F(base + 4); hbp[h] = F(base + 5);
    }

    float *pW, *pcatA, *pcatF, *pq, *pL, *pffh, *pS;
    cudaGetSymbolAddress((void**)&pW,    g_W);
    cudaGetSymbolAddress((void**)&pcatA, g_catA);
    cudaGetSymbolAddress((void**)&pcatF, g_catF);
    cudaGetSymbolAddress((void**)&pq,    g_q);
    cudaGetSymbolAddress((void**)&pL,    g_L);
    cudaGetSymbolAddress((void**)&pffh,  g_ffh);
    cudaGetSymbolAddress((void**)&pS,    g_S);

    float* out = (float*)d_out;

    // dynamic smem sizes: 8 * ST * (BM + BN)
    constexpr int SM128 = 8 * ST * 256;   // 81920 B
    constexpr int SM64  = 8 * ST * 128;   // 40960 B
    cudaFuncSetAttribute(mma_tn<128,128,2,4,true,0>, cudaFuncAttributeMaxDynamicSharedMemorySize, SM128);
    cudaFuncSetAttribute(mma_tn<128,128,2,4,true,1>, cudaFuncAttributeMaxDynamicSharedMemorySize, SM128);
    cudaFuncSetAttribute(mma_tn<64,64,2,2,true,0>,   cudaFuncAttributeMaxDynamicSharedMemorySize, SM64);
    cudaFuncSetAttribute(mma_tn<64,64,2,2,true,2>,   cudaFuncAttributeMaxDynamicSharedMemorySize, SM64);
    cudaFuncSetAttribute(mma_tn<64,64,2,2,true,3>,   cudaFuncAttributeMaxDynamicSharedMemorySize, SM64);
    cudaFuncSetAttribute(mma_tn<64,64,2,2,false,4>,  cudaFuncAttributeMaxDynamicSharedMemorySize, SM64);

    // 1) time-dependent MLPs
    time_mlp_kernel<<<4, 64>>>(t,
        hw0[0], hb0[0], hw1[0], hb1[0],
        hw0[1], hb0[1], hw1[1], hb1[1],
        hw0[2], hb0[2], hw1[2], hb1[2],
        hw0[3], hb0[3], hw1[3], hb1[3]);

    // 2) W = wp @ h + bp (all 4 heads)
    wproj_kernel<<<3840, 256>>>(hwp[0], hbp[0], hwp[1], hbp[1],
                                hwp[2], hbp[2], hwp[3], hbp[3]);

    // 3) LayerNorm -> catA/catF first halves
    ln_kernel<<<4096, 256>>>(slots, F(iLn), F(iLn + 1), F(iLn + 2), F(iLn + 3));

    // 4) q = lnA(slots) @ Wq^T      [4096,256], K=256
    mma_tn<64,64,2,2,true,0><<<dim3(4, 64, 1), 128, SM64>>>(
        pcatA, 512, 0, pW + OFF_WQ, 256, 0, pq, 256, 0,
        256, 1.f, nullptr, 0, 0, nullptr);

    // 5) logits = scale * q @ k^T   per batch [128,4096], K=256
    mma_tn<128,128,2,4,true,0><<<dim3(32, 1, 32), 256, SM128>>>(
        pq, 256, (long long)NS * DD,
        kin, 256, (long long)NF * DD,
        pL, NF, (long long)NS * NF,
        256, 0.0625f, nullptr, 0, 0, nullptr);

    // 6) softmax over slots: per-column max & sum
    colstats_kernel<<<dim3(32, 32), 128>>>();

    // 7) probabilities in-place; row sums S
    rowsum_kernel<<<dim3(128, 32), 256>>>();

    // 8) f_attn = (P @ V) / (S+1e-8) -> catA/catF second halves  (NN form)
    mma_tn<64,64,2,2,false,4><<<dim3(4, 2, 32), 128, SM64>>>(
        pL, NF, (long long)NS * NF,
        vin, DD, (long long)NF * DD,
        pcatA + 256, 512, (long long)NS * 512,
        NF, 1.f, pS, NS, 0, pcatF + 256);

    // 9) out = sigmoid(catA @ Wg^T) * f_attn   [4096,256], K=512
    mma_tn<64,64,2,2,true,2><<<dim3(4, 64, 1), 128, SM64>>>(
        pcatA, 512, 0, pW + OFF_WG, 512, 0, out, 256, 0,
        512, 1.f, pcatA + 256, 0, 512, nullptr);

    // 10) h = relu(catF @ Wf0^T)    [4096,1024], K=512
    mma_tn<128,128,2,4,true,1><<<dim3(8, 32, 1), 256, SM128>>>(
        pcatF, 512, 0, pW + OFF_WF0, 512, 0, pffh, 1024, 0,
        512, 1.f, nullptr, 0, 0, nullptr);

    // 11) out += h @ Wf1^T          [4096,256], K=1024
    mma_tn<64,64,2,2,true,3><<<dim3(4, 64, 1), 128, SM64>>>(
        pffh, 1024, 0, pW + OFF_WF1, 1024, 0, out, 256, 0,
        1024, 1.f, nullptr, 0, 0, nullptr);
}